// round 1
// baseline (speedup 1.0000x reference)
#include <cuda_runtime.h>

#define NL    64      // layers
#define HH    50      // hidden
#define G4    200     // 4*H
#define DIN   60
#define BATCH 32
#define TT    2048
#define DOUT  50
#define BS    16      // batch per CTA
#define NSL   2       // batch slices
#define RINGN 16
#define TPB   224

// ---- scratch (device globals: allocation-free kernel_launch) ----
__device__ float d_ring[(NL - 1) * RINGN * BATCH * HH];   // ~6.5 MB
__device__ int   d_prog[NSL * NL];
__device__ int   d_cons[NSL * NL];
__device__ float d_xT[TT * BATCH * DIN];                  // ~15.7 MB
__device__ float d_outS[TT * BATCH * DOUT];               // ~13.1 MB

// smem layout (floats)
#define OFF_WIH 0        // [K<=60][200]
#define OFF_WHH 12000    // [50][200]
#define OFF_B   22000    // [200]
#define OFF_XS  22200    // [16][64]
#define OFF_HS  23224    // [16][52]
#define OFF_CS  24056    // [16][50]
#define OFF_GS  24856    // [16][200]
#define OFF_FCW 28056    // [50][50]
#define OFF_FCB 30556    // [50]
#define SMEM_FLOATS 30606

__device__ __forceinline__ float sigf(float x) { return 1.0f / (1.0f + __expf(-x)); }

__global__ void init_kernel() {
    int i = threadIdx.x;
    if (i < NSL * NL) { d_prog[i] = 0; d_cons[i] = 0; }
}

__global__ void xpose_kernel(const float* __restrict__ x) {
    int idx = blockIdx.x * blockDim.x + threadIdx.x;  // (b*DIN+d)*T + t
    if (idx >= BATCH * DIN * TT) return;
    int t = idx % TT;
    int bd = idx / TT;
    int d = bd % DIN, b = bd / DIN;
    d_xT[(t * BATCH + b) * DIN + d] = x[idx];
}

__global__ void outpose_kernel(float* __restrict__ out) {
    int idx = blockIdx.x * blockDim.x + threadIdx.x;  // (t*B+b)*DOUT + o
    if (idx >= TT * BATCH * DOUT) return;
    int o = idx % DOUT;
    int tb = idx / DOUT;
    int b = tb % BATCH, t = tb / BATCH;
    out[((size_t)b * DOUT + o) * TT + t] = d_outS[idx];
}

__global__ void __launch_bounds__(TPB, 1) lstm_kernel(
    const float* __restrict__ hn,  const float* __restrict__ cn,
    const float* __restrict__ Wih0, const float* __restrict__ Wih,
    const float* __restrict__ Whh, const float* __restrict__ bih,
    const float* __restrict__ bhh, const float* __restrict__ fcw,
    const float* __restrict__ fcb, float* __restrict__ out, int has_state)
{
    extern __shared__ float sm[];
    const int layer = blockIdx.x >> 1;
    const int s     = blockIdx.x & 1;
    const int b0    = s * BS;
    const int tid   = threadIdx.x;
    const int K1    = (layer == 0) ? DIN : HH;

    float* sm_wih = sm + OFF_WIH;
    float* sm_whh = sm + OFF_WHH;
    float* sm_b   = sm + OFF_B;
    float* sm_xs  = sm + OFF_XS;
    float* sm_hs  = sm + OFF_HS;
    float* sm_cs  = sm + OFF_CS;
    float* sm_gs  = sm + OFF_GS;
    float* sm_fcw = sm + OFF_FCW;
    float* sm_fcb = sm + OFF_FCB;

    // ---- one-time loads: weights transposed to k-major, bias, fc, init state ----
    {
        const float* wg = (layer == 0) ? Wih0 : (Wih + (size_t)(layer - 1) * G4 * HH);
        for (int idx = tid; idx < K1 * G4; idx += TPB) {
            int k = idx / G4, j = idx % G4;
            sm_wih[idx] = wg[j * K1 + k];
        }
        const float* wh = Whh + (size_t)layer * G4 * HH;
        for (int idx = tid; idx < HH * G4; idx += TPB) {
            int k = idx / G4, j = idx % G4;
            sm_whh[idx] = wh[j * HH + k];
        }
        for (int j = tid; j < G4; j += TPB)
            sm_b[j] = bih[layer * G4 + j] + bhh[layer * G4 + j];
        if (layer == NL - 1) {
            for (int i = tid; i < DOUT * HH; i += TPB) sm_fcw[i] = fcw[i];
            for (int i = tid; i < DOUT; i += TPB)      sm_fcb[i] = fcb[i];
        }
        for (int idx = tid; idx < BS * HH; idx += TPB) {
            int b = idx / HH, u = idx % HH;
            sm_hs[b * 52 + u] = hn[((size_t)layer * BATCH + b0 + b) * HH + u];
            sm_cs[b * 50 + u] = cn[((size_t)layer * BATCH + b0 + b) * HH + u];
        }
    }
    __syncthreads();

    volatile int* prog_prev = (layer > 0)      ? (volatile int*)&d_prog[s * NL + layer - 1] : 0;
    volatile int* cons_next = (layer < NL - 1) ? (volatile int*)&d_cons[s * NL + layer + 1] : 0;

    for (int t = 0; t < TT; ++t) {
        // ---- Phase A: wait for input + backpressure, then stage x into smem ----
        if (tid == 0) {
            if (layer > 0)                       { while (*prog_prev < t + 1) __nanosleep(64); }
            if (layer < NL - 1 && t >= RINGN)    { while (*cons_next < t - RINGN + 1) __nanosleep(64); }
            if (layer > 0) __threadfence();  // acquire: invalidate L1 before ring reads
        }
        __syncthreads();
        if (layer == 0) {
            const float* xp = d_xT + ((size_t)t * BATCH + b0) * DIN;
            for (int idx = tid; idx < BS * DIN; idx += TPB) {
                int b = idx / DIN, d = idx % DIN;
                sm_xs[b * 64 + d] = xp[b * DIN + d];
            }
        } else {
            const float* rp = d_ring + (((size_t)(layer - 1) * RINGN + (t & (RINGN - 1))) * BATCH + b0) * HH;
            for (int idx = tid; idx < BS * HH; idx += TPB) {
                int b = idx / HH, u = idx % HH;
                sm_xs[b * 64 + u] = rp[b * HH + u];
            }
        }
        __syncthreads();
        if (tid == 0 && layer > 0) atomicExch(&d_cons[s * NL + layer], t + 1);

        // ---- Phase B: gates = x @ Wih^T + h @ Whh^T + b ----
        if (tid < G4) {
            const int j = tid;
            float acc[BS];
            const float bj = sm_b[j];
#pragma unroll
            for (int b = 0; b < BS; ++b) acc[b] = bj;
#pragma unroll 5
            for (int k = 0; k < K1; k += 2) {
                float w0 = sm_wih[k * G4 + j];
                float w1 = sm_wih[(k + 1) * G4 + j];
#pragma unroll
                for (int b = 0; b < BS; ++b) {
                    float2 xv = *(const float2*)(sm_xs + b * 64 + k);
                    acc[b] = fmaf(xv.x, w0, acc[b]);
                    acc[b] = fmaf(xv.y, w1, acc[b]);
                }
            }
#pragma unroll 5
            for (int k = 0; k < HH; k += 2) {
                float w0 = sm_whh[k * G4 + j];
                float w1 = sm_whh[(k + 1) * G4 + j];
#pragma unroll
                for (int b = 0; b < BS; ++b) {
                    float2 hv = *(const float2*)(sm_hs + b * 52 + k);
                    acc[b] = fmaf(hv.x, w0, acc[b]);
                    acc[b] = fmaf(hv.y, w1, acc[b]);
                }
            }
#pragma unroll
            for (int b = 0; b < BS; ++b) sm_gs[b * G4 + j] = acc[b];
        }
        __syncthreads();

        // ---- Phase C: cell update (i,f,g,o) + publish h into ring ----
        if (tid < G4) {
            const int u  = tid % HH;
            const int bq = tid / HH;  // 0..3
            float* ringp = (layer < NL - 1)
                ? (d_ring + (((size_t)layer * RINGN + (t & (RINGN - 1))) * BATCH + b0) * HH) : 0;
#pragma unroll
            for (int i = 0; i < 4; ++i) {
                int b = bq * 4 + i;
                float gi = sm_gs[b * G4 + u];
                float gf = sm_gs[b * G4 + 50 + u];
                float gg = sm_gs[b * G4 + 100 + u];
                float go = sm_gs[b * G4 + 150 + u];
                float c = sigf(gf) * sm_cs[b * 50 + u] + sigf(gi) * tanhf(gg);
                float h = sigf(go) * tanhf(c);
                sm_cs[b * 50 + u] = c;
                sm_hs[b * 52 + u] = h;
                if (layer < NL - 1) ringp[b * HH + u] = h;
                if (t == TT - 1 && has_state) {
                    size_t base = (size_t)BATCH * DOUT * TT;
                    size_t sidx = ((size_t)layer * BATCH + b0 + b) * HH + u;
                    out[base + sidx] = h;                                   // hs
                    out[base + (size_t)NL * BATCH * HH + sidx] = c;         // cs
                }
            }
        }
        __syncthreads();

        // ---- Phase D: publish progress, or fused FC+sigmoid on last layer ----
        if (layer < NL - 1) {
            if (tid == 0) { __threadfence(); atomicExch(&d_prog[s * NL + layer], t + 1); }
        } else {
            if (tid < G4) {
                const int o  = tid % DOUT;
                const int bq = tid / DOUT;
#pragma unroll
                for (int i = 0; i < 4; ++i) {
                    int b = bq * 4 + i;
                    float acc = sm_fcb[o];
#pragma unroll 5
                    for (int u = 0; u < HH; ++u)
                        acc = fmaf(sm_hs[b * 52 + u], sm_fcw[o * HH + u], acc);
                    d_outS[((size_t)t * BATCH + b0 + b) * DOUT + o] = sigf(acc);
                }
            }
        }
    }
}

extern "C" void kernel_launch(void* const* d_in, const int* in_sizes, int n_in,
                              void* d_out, int out_size) {
    const float* x    = (const float*)d_in[0];
    const float* hn   = (const float*)d_in[1];
    const float* cn   = (const float*)d_in[2];
    const float* Wih0 = (const float*)d_in[3];
    const float* Wih  = (const float*)d_in[4];
    const float* Whh  = (const float*)d_in[5];
    const float* bih  = (const float*)d_in[6];
    const float* bhh  = (const float*)d_in[7];
    const float* fcw  = (const float*)d_in[8];
    const float* fcb  = (const float*)d_in[9];
    float* out = (float*)d_out;

    const long long full = (long long)BATCH * DOUT * TT + 2LL * NL * BATCH * HH;
    int has_state = (out_size >= full) ? 1 : 0;

    cudaFuncSetAttribute(lstm_kernel, cudaFuncAttributeMaxDynamicSharedMemorySize,
                         SMEM_FLOATS * sizeof(float));

    init_kernel<<<1, 256>>>();
    xpose_kernel<<<(BATCH * DIN * TT + 255) / 256, 256>>>(x);
    lstm_kernel<<<NL * NSL, TPB, SMEM_FLOATS * sizeof(float)>>>(
        hn, cn, Wih0, Wih, Whh, bih, bhh, fcw, fcb, out, has_state);
    outpose_kernel<<<(TT * BATCH * DOUT + 255) / 256, 256>>>(out);
}

// round 3
// speedup vs baseline: 1.0988x; 1.0988x over previous
#include <cuda_runtime.h>

#define NL    64      // layers
#define HH    50      // hidden
#define G4    200     // 4*H
#define DIN   60
#define BATCH 32
#define TT    2048
#define DOUT  50
#define BS    16      // batch per CTA
#define NSL   2       // batch slices
#define RINGN 16
#define TPB   224

// ---- scratch (device globals: allocation-free kernel_launch) ----
__device__ float d_ring[(NL - 1) * RINGN * BATCH * HH];
__device__ int   d_prog[NSL * NL];
__device__ int   d_cons[NSL * NL];
__device__ float d_xT[TT * BATCH * DIN];
__device__ float d_outS[TT * BATCH * DOUT];

// smem layout (floats)
#define OFF_WIH 0        // [K<=60][200]  k-major
#define OFF_WHH 12000    // [50][200]     k-major
#define OFF_B   22000    // [200]
#define OFF_XS  22200    // [16][64]
#define OFF_HS  23224    // [16][52]
#define OFF_CS  24056    // [16][50]
#define OFF_GS  24856    // [16][200]
#define OFF_FCW 28056    // [50][50]
#define OFF_FCB 30556    // [50]
#define SMEM_FLOATS 30606

__device__ __forceinline__ float sigf(float x) {
    return __fdividef(1.0f, 1.0f + __expf(-x));   // MUFU.EX2 + MUFU.RCP
}
__device__ __forceinline__ float tanhfast(float x) {
    return 1.0f - __fdividef(2.0f, __expf(2.0f * x) + 1.0f);  // robust at +-inf
}

__device__ __forceinline__ int ld_acquire_gpu(const int* p) {
    int v;
    asm volatile("ld.acquire.gpu.global.b32 %0, [%1];" : "=r"(v) : "l"(p) : "memory");
    return v;
}
__device__ __forceinline__ void st_release_gpu(int* p, int v) {
    asm volatile("st.release.gpu.global.b32 [%0], %1;" :: "l"(p), "r"(v) : "memory");
}

__global__ void init_kernel() {
    int i = threadIdx.x;
    if (i < NSL * NL) { d_prog[i] = 0; d_cons[i] = 0; }
}

__global__ void xpose_kernel(const float* __restrict__ x) {
    int idx = blockIdx.x * blockDim.x + threadIdx.x;  // (b*DIN+d)*T + t
    if (idx >= BATCH * DIN * TT) return;
    int t = idx % TT;
    int bd = idx / TT;
    int d = bd % DIN, b = bd / DIN;
    d_xT[(t * BATCH + b) * DIN + d] = x[idx];
}

__global__ void outpose_kernel(float* __restrict__ out) {
    int idx = blockIdx.x * blockDim.x + threadIdx.x;  // (t*B+b)*DOUT + o
    if (idx >= TT * BATCH * DOUT) return;
    int o = idx % DOUT;
    int tb = idx / DOUT;
    int b = tb % BATCH, t = tb / BATCH;
    out[((size_t)b * DOUT + o) * TT + t] = d_outS[idx];
}

__global__ void __launch_bounds__(TPB, 1) lstm_kernel(
    const float* __restrict__ hn,  const float* __restrict__ cn,
    const float* __restrict__ Wih0, const float* __restrict__ Wih,
    const float* __restrict__ Whh, const float* __restrict__ bih,
    const float* __restrict__ bhh, const float* __restrict__ fcw,
    const float* __restrict__ fcb, float* __restrict__ out, int has_state)
{
    extern __shared__ float sm[];
    const int layer = blockIdx.x >> 1;
    const int s     = blockIdx.x & 1;
    const int b0    = s * BS;
    const int tid   = threadIdx.x;
    const int lane  = tid & 31;
    const int K1    = (layer == 0) ? DIN : HH;

    float* sm_wih = sm + OFF_WIH;
    float* sm_whh = sm + OFF_WHH;
    float* sm_b   = sm + OFF_B;
    float* sm_xs  = sm + OFF_XS;
    float* sm_hs  = sm + OFF_HS;
    float* sm_cs  = sm + OFF_CS;
    float* sm_gs  = sm + OFF_GS;
    float* sm_fcw = sm + OFF_FCW;
    float* sm_fcb = sm + OFF_FCB;

    // ---- one-time loads: weights transposed to k-major, bias, fc, init state ----
    {
        const float* wg = (layer == 0) ? Wih0 : (Wih + (size_t)(layer - 1) * G4 * HH);
        for (int idx = tid; idx < K1 * G4; idx += TPB) {
            int k = idx / G4, j = idx % G4;
            sm_wih[idx] = wg[j * K1 + k];
        }
        const float* wh = Whh + (size_t)layer * G4 * HH;
        for (int idx = tid; idx < HH * G4; idx += TPB) {
            int k = idx / G4, j = idx % G4;
            sm_whh[idx] = wh[j * HH + k];
        }
        for (int j = tid; j < G4; j += TPB)
            sm_b[j] = bih[layer * G4 + j] + bhh[layer * G4 + j];
        if (layer == NL - 1) {
            for (int i = tid; i < DOUT * HH; i += TPB) sm_fcw[i] = fcw[i];
            for (int i = tid; i < DOUT; i += TPB)      sm_fcb[i] = fcb[i];
        }
        for (int idx = tid; idx < BS * HH; idx += TPB) {
            int b = idx / HH, u = idx % HH;
            sm_hs[b * 52 + u] = hn[((size_t)layer * BATCH + b0 + b) * HH + u];
            sm_cs[b * 50 + u] = cn[((size_t)layer * BATCH + b0 + b) * HH + u];
        }
    }
    __syncthreads();

    int* prog_prev = (layer > 0)      ? &d_prog[s * NL + layer - 1] : 0;
    int* cons_next = (layer < NL - 1) ? &d_cons[s * NL + layer + 1] : 0;
    int* prog_me   = &d_prog[s * NL + layer];
    int* cons_me   = &d_cons[s * NL + layer];

    for (int t = 0; t < TT; ++t) {
        float acc[BS];

        // ---- Phase B1: acc = bias + h @ Whh^T  (own previous h; no wait) ----
        if (tid < G4) {
            const int j = tid;
            const float bj = sm_b[j];
#pragma unroll
            for (int b = 0; b < BS; ++b) acc[b] = bj;
#pragma unroll 5
            for (int k = 0; k < HH; k += 2) {
                float w0 = sm_whh[k * G4 + j];
                float w1 = sm_whh[(k + 1) * G4 + j];
#pragma unroll
                for (int b = 0; b < BS; ++b) {
                    float2 hv = *(const float2*)(sm_hs + b * 52 + k);
                    acc[b] = fmaf(hv.x, w0, acc[b]);
                    acc[b] = fmaf(hv.y, w1, acc[b]);
                }
            }
        }

        // ---- Phase A: waits at UNIFORM block scope (all 7 warps fully active) ----
        if (layer > 0) {
            if (lane == 0) { while (ld_acquire_gpu(prog_prev) < t + 1) __nanosleep(32); }
            __syncwarp();
        }
        if (layer < NL - 1 && t >= RINGN) {   // ring backpressure for THIS layer's write
            if (lane == 0) { while (ld_acquire_gpu(cons_next) < t - RINGN + 1) __nanosleep(32); }
            __syncwarp();
        }

        // stage x into smem (ring reads bypass L1 via ldcg)
        if (layer == 0) {
            const float* xp = d_xT + ((size_t)t * BATCH + b0) * DIN;
            for (int idx = tid; idx < BS * DIN; idx += TPB) {
                int b = idx / DIN, d = idx % DIN;
                sm_xs[b * 64 + d] = __ldg(xp + b * DIN + d);
            }
        } else {
            const float* rp = d_ring + (((size_t)(layer - 1) * RINGN + (t & (RINGN - 1))) * BATCH + b0) * HH;
            for (int idx = tid; idx < BS * HH; idx += TPB) {
                int b = idx / HH, u = idx % HH;
                sm_xs[b * 64 + u] = __ldcg(rp + b * HH + u);
            }
        }
        __syncthreads();
        if (tid == 0 && layer > 0) st_release_gpu(cons_me, t + 1);  // slot consumed

        // ---- Phase B2: acc += x @ Wih^T ----
        if (tid < G4) {
            const int j = tid;
#pragma unroll 5
            for (int k = 0; k < K1; k += 2) {
                float w0 = sm_wih[k * G4 + j];
                float w1 = sm_wih[(k + 1) * G4 + j];
#pragma unroll
                for (int b = 0; b < BS; ++b) {
                    float2 xv = *(const float2*)(sm_xs + b * 64 + k);
                    acc[b] = fmaf(xv.x, w0, acc[b]);
                    acc[b] = fmaf(xv.y, w1, acc[b]);
                }
            }
#pragma unroll
            for (int b = 0; b < BS; ++b) sm_gs[b * G4 + j] = acc[b];
        }
        __syncthreads();

        // ---- Phase C: cell update + ring publish (no syncs inside) ----
        if (tid < G4) {
            const int u  = tid % HH;
            const int bq = tid / HH;  // 0..3
            float* ringp = (layer < NL - 1)
                ? (d_ring + (((size_t)layer * RINGN + (t & (RINGN - 1))) * BATCH + b0) * HH) : 0;
#pragma unroll
            for (int i = 0; i < 4; ++i) {
                int b = bq * 4 + i;
                float gi = sm_gs[b * G4 + u];
                float gf = sm_gs[b * G4 + 50 + u];
                float gg = sm_gs[b * G4 + 100 + u];
                float go = sm_gs[b * G4 + 150 + u];
                float c = sigf(gf) * sm_cs[b * 50 + u] + sigf(gi) * tanhfast(gg);
                float h = sigf(go) * tanhfast(c);
                sm_cs[b * 50 + u] = c;
                sm_hs[b * 52 + u] = h;
                if (layer < NL - 1) __stcg(ringp + b * HH + u, h);
                if (t == TT - 1 && has_state) {
                    size_t base = (size_t)BATCH * DOUT * TT;
                    size_t sidx = ((size_t)layer * BATCH + b0 + b) * HH + u;
                    out[base + sidx] = h;                                   // hs
                    out[base + (size_t)NL * BATCH * HH + sidx] = c;         // cs
                }
            }
        }
        __syncthreads();

        // ---- Phase D: publish progress (release), or fused FC+sigmoid on last ----
        if (layer < NL - 1) {
            if (tid == 0) st_release_gpu(prog_me, t + 1);
        } else {
            if (tid < G4) {
                const int o  = tid % DOUT;
                const int bq = tid / DOUT;
#pragma unroll
                for (int i = 0; i < 4; ++i) {
                    int b = bq * 4 + i;
                    float facc = sm_fcb[o];
#pragma unroll 5
                    for (int u = 0; u < HH; ++u)
                        facc = fmaf(sm_hs[b * 52 + u], sm_fcw[o * HH + u], facc);
                    d_outS[((size_t)t * BATCH + b0 + b) * DOUT + o] = sigf(facc);
                }
            }
        }
    }
}

extern "C" void kernel_launch(void* const* d_in, const int* in_sizes, int n_in,
                              void* d_out, int out_size) {
    const float* x    = (const float*)d_in[0];
    const float* hn   = (const float*)d_in[1];
    const float* cn   = (const float*)d_in[2];
    const float* Wih0 = (const float*)d_in[3];
    const float* Wih  = (const float*)d_in[4];
    const float* Whh  = (const float*)d_in[5];
    const float* bih  = (const float*)d_in[6];
    const float* bhh  = (const float*)d_in[7];
    const float* fcw  = (const float*)d_in[8];
    const float* fcb  = (const float*)d_in[9];
    float* out = (float*)d_out;

    const long long full = (long long)BATCH * DOUT * TT + 2LL * NL * BATCH * HH;
    int has_state = (out_size >= full) ? 1 : 0;

    cudaFuncSetAttribute(lstm_kernel, cudaFuncAttributeMaxDynamicSharedMemorySize,
                         SMEM_FLOATS * sizeof(float));

    init_kernel<<<1, 256>>>();
    xpose_kernel<<<(BATCH * DIN * TT + 255) / 256, 256>>>(x);
    lstm_kernel<<<NL * NSL, TPB, SMEM_FLOATS * sizeof(float)>>>(
        hn, cn, Wih0, Wih, Whh, bih, bhh, fcw, fcb, out, has_state);
    outpose_kernel<<<(TT * BATCH * DOUT + 255) / 256, 256>>>(out);
}

// round 4
// speedup vs baseline: 1.2639x; 1.1502x over previous
#include <cuda_runtime.h>

#define NL    64
#define HH    50
#define G4    200
#define DIN   60
#define BATCH 32
#define TT    2048
#define DOUT  50
#define BS    16
#define NSL   2
#define RINGN 16
#define TPB   224

// ---- scratch (device globals) ----
__device__ float d_ring[(NL - 1) * RINGN * HH * BATCH];  // [layer][slot][u][b]
__device__ int   d_prog[NSL * NL];
__device__ int   d_cons[NSL * NL];
__device__ float d_xT[TT * DIN * BATCH];                 // [t][d][b]
__device__ float d_outS[TT * BATCH * DOUT];

// smem layout (floats)
#define OFF_WIH 0        // [K<=60][200]  k-major
#define OFF_WHH 12000    // [50][200]     k-major
#define OFF_B   22000    // [200]
#define OFF_XS  22200    // [60][20]  k-major, b fastest (cols 0..15 used)
#define OFF_HS  23400    // [50][20]
#define OFF_GS  24400    // [16][200]
#define OFF_FCW 27600    // [50][50]
#define OFF_FCB 30100    // [50]
#define SMEM_FLOATS 30152

__device__ __forceinline__ float sigf(float x) {
    return __fdividef(1.0f, 1.0f + __expf(-x));
}
__device__ __forceinline__ float tanhfast(float x) {
    return 1.0f - __fdividef(2.0f, __expf(2.0f * x) + 1.0f);
}

__device__ __forceinline__ unsigned long long pack2(float x) {
    unsigned long long r;
    asm("mov.b64 %0, {%1, %1};" : "=l"(r) : "f"(x));
    return r;
}
__device__ __forceinline__ void fma2(unsigned long long& d, unsigned long long a,
                                     unsigned long long b) {
    asm("fma.rn.f32x2 %0, %1, %2, %0;" : "+l"(d) : "l"(a), "l"(b));
}
__device__ __forceinline__ void unpack2(unsigned long long v, float& lo, float& hi) {
    asm("mov.b64 {%0, %1}, %2;" : "=f"(lo), "=f"(hi) : "l"(v));
}

__device__ __forceinline__ int ld_acquire_gpu(const int* p) {
    int v;
    asm volatile("ld.acquire.gpu.global.b32 %0, [%1];" : "=r"(v) : "l"(p) : "memory");
    return v;
}
__device__ __forceinline__ void st_release_gpu(int* p, int v) {
    asm volatile("st.release.gpu.global.b32 [%0], %1;" :: "l"(p), "r"(v) : "memory");
}

__global__ void init_kernel() {
    int i = threadIdx.x;
    if (i < NSL * NL) { d_prog[i] = 0; d_cons[i] = 0; }
}

__global__ void xpose_kernel(const float* __restrict__ x) {
    int idx = blockIdx.x * blockDim.x + threadIdx.x;  // (b*DIN+d)*T + t
    if (idx >= BATCH * DIN * TT) return;
    int t = idx % TT;
    int bd = idx / TT;
    int d = bd % DIN, b = bd / DIN;
    d_xT[((size_t)t * DIN + d) * BATCH + b] = x[idx];
}

__global__ void outpose_kernel(float* __restrict__ out) {
    int idx = blockIdx.x * blockDim.x + threadIdx.x;  // (t*B+b)*DOUT + o
    if (idx >= TT * BATCH * DOUT) return;
    int o = idx % DOUT;
    int tb = idx / DOUT;
    int b = tb % BATCH, t = tb / BATCH;
    out[((size_t)b * DOUT + o) * TT + t] = d_outS[idx];
}

__global__ void __launch_bounds__(TPB, 1) lstm_kernel(
    const float* __restrict__ hn,  const float* __restrict__ cn,
    const float* __restrict__ Wih0, const float* __restrict__ Wih,
    const float* __restrict__ Whh, const float* __restrict__ bih,
    const float* __restrict__ bhh, const float* __restrict__ fcw,
    const float* __restrict__ fcb, float* __restrict__ out, int has_state)
{
    extern __shared__ float sm[];
    const int layer = blockIdx.x >> 1;
    const int s     = blockIdx.x & 1;
    const int b0    = s * BS;
    const int tid   = threadIdx.x;
    const int lane  = tid & 31;
    const int K1    = (layer == 0) ? DIN : HH;

    float* sm_wih = sm + OFF_WIH;
    float* sm_whh = sm + OFF_WHH;
    float* sm_b   = sm + OFF_B;
    float* sm_xs  = sm + OFF_XS;
    float* sm_hs  = sm + OFF_HS;
    float* sm_gs  = sm + OFF_GS;
    float* sm_fcw = sm + OFF_FCW;
    float* sm_fcb = sm + OFF_FCB;

    // ---- one-time loads ----
    {
        const float* wg = (layer == 0) ? Wih0 : (Wih + (size_t)(layer - 1) * G4 * HH);
        for (int idx = tid; idx < K1 * G4; idx += TPB) {
            int k = idx / G4, j = idx % G4;
            sm_wih[idx] = wg[j * K1 + k];
        }
        const float* wh = Whh + (size_t)layer * G4 * HH;
        for (int idx = tid; idx < HH * G4; idx += TPB) {
            int k = idx / G4, j = idx % G4;
            sm_whh[idx] = wh[j * HH + k];
        }
        for (int j = tid; j < G4; j += TPB)
            sm_b[j] = bih[layer * G4 + j] + bhh[layer * G4 + j];
        if (layer == NL - 1) {
            for (int i = tid; i < DOUT * HH; i += TPB) sm_fcw[i] = fcw[i];
            for (int i = tid; i < DOUT; i += TPB)      sm_fcb[i] = fcb[i];
        }
        // h0 into k-major sm_hs
        for (int idx = tid; idx < BS * HH; idx += TPB) {
            int u = idx / BS, b = idx % BS;
            sm_hs[u * 20 + b] = hn[((size_t)layer * BATCH + b0 + b) * HH + u];
        }
    }
    // c0 into registers: thread (u = tid%50, bq = tid/50) owns b = bq*4..bq*4+3
    float creg[4];
    const int u_c  = tid % HH;
    const int bq_c = (tid < G4) ? (tid / HH) : 0;
    if (tid < G4) {
#pragma unroll
        for (int i = 0; i < 4; ++i)
            creg[i] = cn[((size_t)layer * BATCH + b0 + bq_c * 4 + i) * HH + u_c];
    }
    __syncthreads();

    int* prog_prev = (layer > 0)      ? &d_prog[s * NL + layer - 1] : 0;
    int* cons_next = (layer < NL - 1) ? &d_cons[s * NL + layer + 1] : 0;
    int* prog_me   = &d_prog[s * NL + layer];
    int* cons_me   = &d_cons[s * NL + layer];

    for (int t = 0; t < TT; ++t) {
        unsigned long long acc2[8];

        // ---- Phase B1: acc = bias + h @ Whh^T (packed f32x2, own h, no wait) ----
        if (tid < G4) {
            unsigned long long bj2 = pack2(sm_b[tid]);
#pragma unroll
            for (int p = 0; p < 8; ++p) acc2[p] = bj2;
#pragma unroll 5
            for (int k = 0; k < HH; ++k) {
                unsigned long long w2 = pack2(sm_whh[k * G4 + tid]);
                const ulonglong2* hp = (const ulonglong2*)(sm_hs + k * 20);
                ulonglong2 q0 = hp[0], q1 = hp[1], q2 = hp[2], q3 = hp[3];
                fma2(acc2[0], q0.x, w2); fma2(acc2[1], q0.y, w2);
                fma2(acc2[2], q1.x, w2); fma2(acc2[3], q1.y, w2);
                fma2(acc2[4], q2.x, w2); fma2(acc2[5], q2.y, w2);
                fma2(acc2[6], q3.x, w2); fma2(acc2[7], q3.y, w2);
            }
        }

        // ---- Phase A: waits at uniform block scope ----
        if (layer > 0) {
            if (lane == 0) { while (ld_acquire_gpu(prog_prev) < t + 1) __nanosleep(32); }
            __syncwarp();
        }
        if (layer < NL - 1 && t >= RINGN) {
            if (lane == 0) { while (ld_acquire_gpu(cons_next) < t - RINGN + 1) __nanosleep(32); }
            __syncwarp();
        }
        // stage x k-major as float4 (count = K1*4 quads)
        if (layer == 0) {
            for (int idx = tid; idx < K1 * 4; idx += TPB) {
                int d = idx >> 2, q = idx & 3;
                float4 v = *(const float4*)(d_xT + ((size_t)t * DIN + d) * BATCH + b0 + q * 4);
                *(float4*)(sm_xs + d * 20 + q * 4) = v;
            }
        } else {
            const float* rp = d_ring + (((size_t)(layer - 1) * RINGN + (t & (RINGN - 1))) * HH) * BATCH;
            for (int idx = tid; idx < HH * 4; idx += TPB) {
                int u = idx >> 2, q = idx & 3;
                float4 v = __ldcg((const float4*)(rp + u * BATCH + b0 + q * 4));
                *(float4*)(sm_xs + u * 20 + q * 4) = v;
            }
        }
        __syncthreads();
        if (tid == 0 && layer > 0) st_release_gpu(cons_me, t + 1);

        // ---- Phase B2: acc += x @ Wih^T ----
        if (tid < G4) {
#pragma unroll 5
            for (int k = 0; k < K1; ++k) {
                unsigned long long w2 = pack2(sm_wih[k * G4 + tid]);
                const ulonglong2* xp = (const ulonglong2*)(sm_xs + k * 20);
                ulonglong2 q0 = xp[0], q1 = xp[1], q2 = xp[2], q3 = xp[3];
                fma2(acc2[0], q0.x, w2); fma2(acc2[1], q0.y, w2);
                fma2(acc2[2], q1.x, w2); fma2(acc2[3], q1.y, w2);
                fma2(acc2[4], q2.x, w2); fma2(acc2[5], q2.y, w2);
                fma2(acc2[6], q3.x, w2); fma2(acc2[7], q3.y, w2);
            }
#pragma unroll
            for (int p = 0; p < 8; ++p) {
                float lo, hi;
                unpack2(acc2[p], lo, hi);
                sm_gs[(2 * p)     * G4 + tid] = lo;
                sm_gs[(2 * p + 1) * G4 + tid] = hi;
            }
        }
        __syncthreads();

        // ---- Phase C: cell update (c in regs), h -> smem + ring (STG.128) ----
        if (tid < G4) {
            const int u  = u_c;
            const int bq = bq_c;
            float h4[4];
#pragma unroll
            for (int i = 0; i < 4; ++i) {
                int b = bq * 4 + i;
                float gi = sm_gs[b * G4 + u];
                float gf = sm_gs[b * G4 + 50 + u];
                float gg = sm_gs[b * G4 + 100 + u];
                float go = sm_gs[b * G4 + 150 + u];
                float c = sigf(gf) * creg[i] + sigf(gi) * tanhfast(gg);
                float h = sigf(go) * tanhfast(c);
                creg[i] = c;
                h4[i] = h;
                sm_hs[u * 20 + b] = h;
            }
            if (layer < NL - 1) {
                float4 hv = make_float4(h4[0], h4[1], h4[2], h4[3]);
                __stcg((float4*)(d_ring +
                       (((size_t)layer * RINGN + (t & (RINGN - 1))) * HH + u) * BATCH + b0 + bq * 4), hv);
            }
            if (t == TT - 1 && has_state) {
                size_t base = (size_t)BATCH * DOUT * TT;
#pragma unroll
                for (int i = 0; i < 4; ++i) {
                    size_t sidx = ((size_t)layer * BATCH + b0 + bq * 4 + i) * HH + u;
                    out[base + sidx] = h4[i];
                    out[base + (size_t)NL * BATCH * HH + sidx] = creg[i];
                }
            }
        }
        __syncthreads();

        // ---- Phase D: publish progress, or fused FC+sigmoid on last layer ----
        if (layer < NL - 1) {
            if (tid == 0) st_release_gpu(prog_me, t + 1);
        } else {
            if (tid < G4) {
                const int o  = tid % DOUT;
                const int bq = tid / DOUT;
#pragma unroll
                for (int i = 0; i < 4; ++i) {
                    int b = bq * 4 + i;
                    float facc = sm_fcb[o];
#pragma unroll 5
                    for (int u = 0; u < HH; ++u)
                        facc = fmaf(sm_hs[u * 20 + b], sm_fcw[o * HH + u], facc);
                    d_outS[((size_t)t * BATCH + b0 + b) * DOUT + o] = sigf(facc);
                }
            }
        }
    }
}

extern "C" void kernel_launch(void* const* d_in, const int* in_sizes, int n_in,
                              void* d_out, int out_size) {
    const float* x    = (const float*)d_in[0];
    const float* hn   = (const float*)d_in[1];
    const float* cn   = (const float*)d_in[2];
    const float* Wih0 = (const float*)d_in[3];
    const float* Wih  = (const float*)d_in[4];
    const float* Whh  = (const float*)d_in[5];
    const float* bih  = (const float*)d_in[6];
    const float* bhh  = (const float*)d_in[7];
    const float* fcw  = (const float*)d_in[8];
    const float* fcb  = (const float*)d_in[9];
    float* out = (float*)d_out;

    const long long full = (long long)BATCH * DOUT * TT + 2LL * NL * BATCH * HH;
    int has_state = (out_size >= full) ? 1 : 0;

    cudaFuncSetAttribute(lstm_kernel, cudaFuncAttributeMaxDynamicSharedMemorySize,
                         SMEM_FLOATS * sizeof(float));

    init_kernel<<<1, 256>>>();
    xpose_kernel<<<(BATCH * DIN * TT + 255) / 256, 256>>>(x);
    lstm_kernel<<<NL * NSL, TPB, SMEM_FLOATS * sizeof(float)>>>(
        hn, cn, Wih0, Wih, Whh, bih, bhh, fcw, fcb, out, has_state);
    outpose_kernel<<<(TT * BATCH * DOUT + 255) / 256, 256>>>(out);
}

// round 5
// speedup vs baseline: 1.6886x; 1.3360x over previous
#include <cuda_runtime.h>

#define NL    64
#define HH    50
#define G4    200
#define DIN   60
#define BATCH 32
#define TT    2048
#define DOUT  50
#define BS    16
#define NSL   2
#define RINGN 16
#define TPB   224

// ---- scratch (device globals) ----
__device__ float d_ring[(NL - 1) * RINGN * HH * BATCH];  // [layer][slot][u][b]
__device__ int   d_prog[NSL * NL];
__device__ int   d_cons[NSL * NL];
__device__ float d_xT[TT * DIN * BATCH];                 // [t][d][b]
__device__ float d_hT[TT * HH * BATCH];                  // [t][u][b]  layer-63 h

// lstm smem layout (floats)
#define OFF_WIH 0        // [K<=60][200]  k-major
#define OFF_WHH 12000    // [50][200]     k-major
#define OFF_B   22000    // [200]
#define OFF_XS  22200    // [60][20]
#define OFF_HS  23400    // [50][20]
#define OFF_GS  24400    // [16][200]
#define SMEM_FLOATS 27600
// fc smem layout (floats) — separate role, same dynamic smem
#define FOFF_W  0        // [50][50]
#define FOFF_B  2500     // [50]
#define FOFF_H  2560     // [50][16]

__device__ __forceinline__ float sigf(float x) {
    return __fdividef(1.0f, 1.0f + __expf(-x));
}
__device__ __forceinline__ float tanhfast(float x) {
    return 1.0f - __fdividef(2.0f, __expf(2.0f * x) + 1.0f);
}

__device__ __forceinline__ unsigned long long pack2(float x) {
    unsigned long long r;
    asm("mov.b64 %0, {%1, %1};" : "=l"(r) : "f"(x));
    return r;
}
__device__ __forceinline__ void fma2(unsigned long long& d, unsigned long long a,
                                     unsigned long long b) {
    asm("fma.rn.f32x2 %0, %1, %2, %0;" : "+l"(d) : "l"(a), "l"(b));
}
__device__ __forceinline__ void unpack2(unsigned long long v, float& lo, float& hi) {
    asm("mov.b64 {%0, %1}, %2;" : "=f"(lo), "=f"(hi) : "l"(v));
}

__device__ __forceinline__ int ld_acquire_gpu(const int* p) {
    int v;
    asm volatile("ld.acquire.gpu.global.b32 %0, [%1];" : "=r"(v) : "l"(p) : "memory");
    return v;
}
__device__ __forceinline__ void st_release_gpu(int* p, int v) {
    asm volatile("st.release.gpu.global.b32 [%0], %1;" :: "l"(p), "r"(v) : "memory");
}

// xpose + flag init fused (block 0 does init; kernel completes before lstm)
__global__ void xpose_kernel(const float* __restrict__ x) {
    if (blockIdx.x == 0 && threadIdx.x < NSL * NL) {
        d_prog[threadIdx.x] = 0;
        d_cons[threadIdx.x] = 0;
    }
    int idx = blockIdx.x * blockDim.x + threadIdx.x;  // (b*DIN+d)*T + t
    if (idx >= BATCH * DIN * TT) return;
    int t = idx % TT;
    int bd = idx / TT;
    int d = bd % DIN, b = bd / DIN;
    d_xT[((size_t)t * DIN + d) * BATCH + b] = x[idx];
}

__global__ void __launch_bounds__(TPB, 1) lstm_kernel(
    const float* __restrict__ hn,  const float* __restrict__ cn,
    const float* __restrict__ Wih0, const float* __restrict__ Wih,
    const float* __restrict__ Whh, const float* __restrict__ bih,
    const float* __restrict__ bhh, const float* __restrict__ fcw,
    const float* __restrict__ fcb, float* __restrict__ out, int has_state)
{
    extern __shared__ float sm[];
    const int tid  = threadIdx.x;
    const int lane = tid & 31;

    // ================= FC consumer role (blocks 128,129) =================
    if (blockIdx.x >= NL * NSL) {
        const int s  = blockIdx.x - NL * NSL;
        const int b0 = s * BS;
        float* sm_w = sm + FOFF_W;
        float* sm_fb = sm + FOFF_B;
        float* sm_h = sm + FOFF_H;
        for (int i = tid; i < DOUT * HH; i += TPB) sm_w[i] = fcw[i];
        for (int i = tid; i < DOUT; i += TPB)      sm_fb[i] = fcb[i];
        __syncthreads();
        const int* prog63 = &d_prog[s * NL + NL - 1];
        for (int t = 0; t < TT; ++t) {
            if (lane == 0) { while (ld_acquire_gpu(prog63) < t + 1) __nanosleep(128); }
            __syncwarp();
            // stage h[50][16] for this slice
            for (int idx = tid; idx < HH * 4; idx += TPB) {
                int u = idx >> 2, q = idx & 3;
                float4 v = __ldcg((const float4*)(d_hT + ((size_t)t * HH + u) * BATCH + b0 + q * 4));
                *(float4*)(sm_h + u * 16 + q * 4) = v;
            }
            __syncthreads();
            if (tid < G4) {
                const int o  = tid % DOUT;
                const int bq = tid / DOUT;
#pragma unroll
                for (int i = 0; i < 4; ++i) {
                    int b = bq * 4 + i;
                    float acc = sm_fb[o];
#pragma unroll 5
                    for (int u = 0; u < HH; ++u)
                        acc = fmaf(sm_h[u * 16 + b], sm_w[o * HH + u], acc);
                    out[((size_t)(b0 + b) * DOUT + o) * TT + t] = sigf(acc);
                }
            }
            __syncthreads();
        }
        return;
    }

    // ========================= LSTM layer role =========================
    const int layer = blockIdx.x >> 1;
    const int s     = blockIdx.x & 1;
    const int b0    = s * BS;
    const int K1    = (layer == 0) ? DIN : HH;

    float* sm_wih = sm + OFF_WIH;
    float* sm_whh = sm + OFF_WHH;
    float* sm_b   = sm + OFF_B;
    float* sm_xs  = sm + OFF_XS;
    float* sm_hs  = sm + OFF_HS;
    float* sm_gs  = sm + OFF_GS;

    {
        const float* wg = (layer == 0) ? Wih0 : (Wih + (size_t)(layer - 1) * G4 * HH);
        for (int idx = tid; idx < K1 * G4; idx += TPB) {
            int k = idx / G4, j = idx % G4;
            sm_wih[idx] = wg[j * K1 + k];
        }
        const float* wh = Whh + (size_t)layer * G4 * HH;
        for (int idx = tid; idx < HH * G4; idx += TPB) {
            int k = idx / G4, j = idx % G4;
            sm_whh[idx] = wh[j * HH + k];
        }
        for (int j = tid; j < G4; j += TPB)
            sm_b[j] = bih[layer * G4 + j] + bhh[layer * G4 + j];
        for (int idx = tid; idx < BS * HH; idx += TPB) {
            int u = idx / BS, b = idx % BS;
            sm_hs[u * 20 + b] = hn[((size_t)layer * BATCH + b0 + b) * HH + u];
        }
    }
    float creg[4];
    const int u_c  = tid % HH;
    const int bq_c = (tid < G4) ? (tid / HH) : 0;
    if (tid < G4) {
#pragma unroll
        for (int i = 0; i < 4; ++i)
            creg[i] = cn[((size_t)layer * BATCH + b0 + bq_c * 4 + i) * HH + u_c];
    }
    __syncthreads();

    int* prog_prev = (layer > 0)      ? &d_prog[s * NL + layer - 1] : 0;
    int* cons_next = (layer < NL - 1) ? &d_cons[s * NL + layer + 1] : 0;
    int* prog_me   = &d_prog[s * NL + layer];
    int* cons_me   = &d_cons[s * NL + layer];

    for (int t = 0; t < TT; ++t) {
        unsigned long long acc2[8];

        // ---- B1: acc = bias + h @ Whh^T (own h, no wait) ----
        if (tid < G4) {
            unsigned long long bj2 = pack2(sm_b[tid]);
#pragma unroll
            for (int p = 0; p < 8; ++p) acc2[p] = bj2;
#pragma unroll 5
            for (int k = 0; k < HH; ++k) {
                unsigned long long w2 = pack2(sm_whh[k * G4 + tid]);
                const ulonglong2* hp = (const ulonglong2*)(sm_hs + k * 20);
                ulonglong2 q0 = hp[0], q1 = hp[1], q2 = hp[2], q3 = hp[3];
                fma2(acc2[0], q0.x, w2); fma2(acc2[1], q0.y, w2);
                fma2(acc2[2], q1.x, w2); fma2(acc2[3], q1.y, w2);
                fma2(acc2[4], q2.x, w2); fma2(acc2[5], q2.y, w2);
                fma2(acc2[6], q3.x, w2); fma2(acc2[7], q3.y, w2);
            }
        }

        // ---- A: waits (uniform block scope) + stage x ----
        if (layer > 0) {
            if (lane == 0) { while (ld_acquire_gpu(prog_prev) < t + 1) __nanosleep(32); }
            __syncwarp();
        }
        if (layer < NL - 1 && t >= RINGN) {
            if (lane == 0) { while (ld_acquire_gpu(cons_next) < t - RINGN + 1) __nanosleep(32); }
            __syncwarp();
        }
        if (layer == 0) {
            for (int idx = tid; idx < K1 * 4; idx += TPB) {
                int d = idx >> 2, q = idx & 3;
                float4 v = *(const float4*)(d_xT + ((size_t)t * DIN + d) * BATCH + b0 + q * 4);
                *(float4*)(sm_xs + d * 20 + q * 4) = v;
            }
        } else {
            const float* rp = d_ring + (((size_t)(layer - 1) * RINGN + (t & (RINGN - 1))) * HH) * BATCH;
            for (int idx = tid; idx < HH * 4; idx += TPB) {
                int u = idx >> 2, q = idx & 3;
                float4 v = __ldcg((const float4*)(rp + u * BATCH + b0 + q * 4));
                *(float4*)(sm_xs + u * 20 + q * 4) = v;
            }
        }
        __syncthreads();
        if (tid == 0 && layer > 0 && (((t & 3) == 3) || t == TT - 1))
            st_release_gpu(cons_me, t + 1);   // batched consumption publish

        // ---- B2: acc += x @ Wih^T ----
        if (tid < G4) {
#pragma unroll 5
            for (int k = 0; k < K1; ++k) {
                unsigned long long w2 = pack2(sm_wih[k * G4 + tid]);
                const ulonglong2* xp = (const ulonglong2*)(sm_xs + k * 20);
                ulonglong2 q0 = xp[0], q1 = xp[1], q2 = xp[2], q3 = xp[3];
                fma2(acc2[0], q0.x, w2); fma2(acc2[1], q0.y, w2);
                fma2(acc2[2], q1.x, w2); fma2(acc2[3], q1.y, w2);
                fma2(acc2[4], q2.x, w2); fma2(acc2[5], q2.y, w2);
                fma2(acc2[6], q3.x, w2); fma2(acc2[7], q3.y, w2);
            }
#pragma unroll
            for (int p = 0; p < 8; ++p) {
                float lo, hi;
                unpack2(acc2[p], lo, hi);
                sm_gs[(2 * p)     * G4 + tid] = lo;
                sm_gs[(2 * p + 1) * G4 + tid] = hi;
            }
        }
        __syncthreads();

        // ---- C: cell update (c in regs), publish h (ring or d_hT) ----
        if (tid < G4) {
            const int u  = u_c;
            const int bq = bq_c;
            float h4[4];
#pragma unroll
            for (int i = 0; i < 4; ++i) {
                int b = bq * 4 + i;
                float gi = sm_gs[b * G4 + u];
                float gf = sm_gs[b * G4 + 50 + u];
                float gg = sm_gs[b * G4 + 100 + u];
                float go = sm_gs[b * G4 + 150 + u];
                float c = sigf(gf) * creg[i] + sigf(gi) * tanhfast(gg);
                float h = sigf(go) * tanhfast(c);
                creg[i] = c;
                h4[i] = h;
                sm_hs[u * 20 + b] = h;
            }
            float4 hv = make_float4(h4[0], h4[1], h4[2], h4[3]);
            float* dst = (layer < NL - 1)
                ? (d_ring + (((size_t)layer * RINGN + (t & (RINGN - 1))) * HH + u) * BATCH + b0 + bq * 4)
                : (d_hT + ((size_t)t * HH + u) * BATCH + b0 + bq * 4);
            __stcg((float4*)dst, hv);
            if (t == TT - 1 && has_state) {
                size_t base = (size_t)BATCH * DOUT * TT;
#pragma unroll
                for (int i = 0; i < 4; ++i) {
                    size_t sidx = ((size_t)layer * BATCH + b0 + bq * 4 + i) * HH + u;
                    out[base + sidx] = h4[i];
                    out[base + (size_t)NL * BATCH * HH + sidx] = creg[i];
                }
            }
        }
        __syncthreads();

        // ---- D: publish progress (all layers; layer 63's consumer is FC CTA) ----
        if (tid == 0) st_release_gpu(prog_me, t + 1);
    }
}

extern "C" void kernel_launch(void* const* d_in, const int* in_sizes, int n_in,
                              void* d_out, int out_size) {
    const float* x    = (const float*)d_in[0];
    const float* hn   = (const float*)d_in[1];
    const float* cn   = (const float*)d_in[2];
    const float* Wih0 = (const float*)d_in[3];
    const float* Wih  = (const float*)d_in[4];
    const float* Whh  = (const float*)d_in[5];
    const float* bih  = (const float*)d_in[6];
    const float* bhh  = (const float*)d_in[7];
    const float* fcw  = (const float*)d_in[8];
    const float* fcb  = (const float*)d_in[9];
    float* out = (float*)d_out;

    const long long full = (long long)BATCH * DOUT * TT + 2LL * NL * BATCH * HH;
    int has_state = (out_size >= full) ? 1 : 0;

    cudaFuncSetAttribute(lstm_kernel, cudaFuncAttributeMaxDynamicSharedMemorySize,
                         SMEM_FLOATS * sizeof(float));

    xpose_kernel<<<(BATCH * DIN * TT + 255) / 256, 256>>>(x);
    lstm_kernel<<<NL * NSL + NSL, TPB, SMEM_FLOATS * sizeof(float)>>>(
        hn, cn, Wih0, Wih, Whh, bih, bhh, fcw, fcb, out, has_state);
}

// round 6
// speedup vs baseline: 1.6896x; 1.0006x over previous
#include <cuda_runtime.h>

#define NL    64
#define HH    50
#define G4    200
#define DIN   60
#define BATCH 32
#define TT    2048
#define DOUT  50
#define BS    16
#define NSL   2
#define RINGN 16
#define TPB   416    // 13 warps; threads 0..399 active in compute phases

// ---- scratch (device globals) ----
__device__ float d_ring[(NL - 1) * RINGN * HH * BATCH];  // [layer][slot][u][b]
__device__ int   d_prog[NSL * NL];
__device__ int   d_cons[NSL * NL];
__device__ float d_xT[TT * DIN * BATCH];                 // [t][d][b]
__device__ float d_hT[TT * HH * BATCH];                  // [t][u][b]  layer-63 h

// lstm smem layout (floats)
#define OFF_WIH 0        // [K<=60][200]  k-major
#define OFF_WHH 12000    // [50][200]     k-major
#define OFF_B   22000    // [200]
#define OFF_XS  22200    // [60][20]
#define OFF_HS  23400    // [50][20]
#define OFF_GS  24400    // [16][200]
#define SMEM_FLOATS 27600
// fc smem layout (floats)
#define FOFF_W  0        // [50][50]
#define FOFF_B  2500     // [50]
#define FOFF_H  2560     // [50][16]

__device__ __forceinline__ float sigf(float x) {
    return __fdividef(1.0f, 1.0f + __expf(-x));
}
__device__ __forceinline__ float tanhfast(float x) {
    return 1.0f - __fdividef(2.0f, __expf(2.0f * x) + 1.0f);
}

__device__ __forceinline__ unsigned long long pack2(float x) {
    unsigned long long r;
    asm("mov.b64 %0, {%1, %1};" : "=l"(r) : "f"(x));
    return r;
}
__device__ __forceinline__ void fma2(unsigned long long& d, unsigned long long a,
                                     unsigned long long b) {
    asm("fma.rn.f32x2 %0, %1, %2, %0;" : "+l"(d) : "l"(a), "l"(b));
}
__device__ __forceinline__ void unpack2(unsigned long long v, float& lo, float& hi) {
    asm("mov.b64 {%0, %1}, %2;" : "=f"(lo), "=f"(hi) : "l"(v));
}

__device__ __forceinline__ int ld_acquire_gpu(const int* p) {
    int v;
    asm volatile("ld.acquire.gpu.global.b32 %0, [%1];" : "=r"(v) : "l"(p) : "memory");
    return v;
}
__device__ __forceinline__ void st_release_gpu(int* p, int v) {
    asm volatile("st.release.gpu.global.b32 [%0], %1;" :: "l"(p), "r"(v) : "memory");
}

__global__ void xpose_kernel(const float* __restrict__ x) {
    if (blockIdx.x == 0 && threadIdx.x < NSL * NL) {
        d_prog[threadIdx.x] = 0;
        d_cons[threadIdx.x] = 0;
    }
    int idx = blockIdx.x * blockDim.x + threadIdx.x;  // (b*DIN+d)*T + t
    if (idx >= BATCH * DIN * TT) return;
    int t = idx % TT;
    int bd = idx / TT;
    int d = bd % DIN, b = bd / DIN;
    d_xT[((size_t)t * DIN + d) * BATCH + b] = x[idx];
}

__global__ void __launch_bounds__(TPB, 1) lstm_kernel(
    const float* __restrict__ hn,  const float* __restrict__ cn,
    const float* __restrict__ Wih0, const float* __restrict__ Wih,
    const float* __restrict__ Whh, const float* __restrict__ bih,
    const float* __restrict__ bhh, const float* __restrict__ fcw,
    const float* __restrict__ fcb, float* __restrict__ out, int has_state)
{
    extern __shared__ float sm[];
    const int tid  = threadIdx.x;
    const int lane = tid & 31;

    // ================= FC consumer role (blocks 128,129) =================
    if (blockIdx.x >= NL * NSL) {
        const int s  = blockIdx.x - NL * NSL;
        const int b0 = s * BS;
        float* sm_w = sm + FOFF_W;
        float* sm_fb = sm + FOFF_B;
        float* sm_h = sm + FOFF_H;
        for (int i = tid; i < DOUT * HH; i += TPB) sm_w[i] = fcw[i];
        for (int i = tid; i < DOUT; i += TPB)      sm_fb[i] = fcb[i];
        __syncthreads();
        const int* prog63 = &d_prog[s * NL + NL - 1];
        for (int t = 0; t < TT; ++t) {
            if (lane == 0) { while (ld_acquire_gpu(prog63) < t + 1) __nanosleep(128); }
            __syncwarp();
            for (int idx = tid; idx < HH * 4; idx += TPB) {
                int u = idx >> 2, q = idx & 3;
                float4 v = __ldcg((const float4*)(d_hT + ((size_t)t * HH + u) * BATCH + b0 + q * 4));
                *(float4*)(sm_h + u * 16 + q * 4) = v;
            }
            __syncthreads();
            if (tid < G4) {
                const int o  = tid % DOUT;
                const int bq = tid / DOUT;
#pragma unroll
                for (int i = 0; i < 4; ++i) {
                    int b = bq * 4 + i;
                    float acc = sm_fb[o];
#pragma unroll 5
                    for (int u = 0; u < HH; ++u)
                        acc = fmaf(sm_h[u * 16 + b], sm_w[o * HH + u], acc);
                    out[((size_t)(b0 + b) * DOUT + o) * TT + t] = sigf(acc);
                }
            }
            __syncthreads();
        }
        return;
    }

    // ========================= LSTM layer role =========================
    const int layer = blockIdx.x >> 1;
    const int s     = blockIdx.x & 1;
    const int b0    = s * BS;
    const int K1    = (layer == 0) ? DIN : HH;

    float* sm_wih = sm + OFF_WIH;
    float* sm_whh = sm + OFF_WHH;
    float* sm_b   = sm + OFF_B;
    float* sm_xs  = sm + OFF_XS;
    float* sm_hs  = sm + OFF_HS;
    float* sm_gs  = sm + OFF_GS;

    {
        const float* wg = (layer == 0) ? Wih0 : (Wih + (size_t)(layer - 1) * G4 * HH);
        for (int idx = tid; idx < K1 * G4; idx += TPB) {
            int k = idx / G4, j = idx % G4;
            sm_wih[idx] = wg[j * K1 + k];
        }
        const float* wh = Whh + (size_t)layer * G4 * HH;
        for (int idx = tid; idx < HH * G4; idx += TPB) {
            int k = idx / G4, j = idx % G4;
            sm_whh[idx] = wh[j * HH + k];
        }
        for (int j = tid; j < G4; j += TPB)
            sm_b[j] = bih[layer * G4 + j] + bhh[layer * G4 + j];
        for (int idx = tid; idx < BS * HH; idx += TPB) {
            int u = idx / BS, b = idx % BS;
            sm_hs[u * 20 + b] = hn[((size_t)layer * BATCH + b0 + b) * HH + u];
        }
    }
    // c in regs: thread (u = tid%50, bq = tid/50 in 0..7) owns b = bq*2, bq*2+1
    float creg[2];
    const int u_c  = tid % HH;
    const int bq_c = (tid < 400) ? (tid / HH) : 0;
    if (tid < 400) {
#pragma unroll
        for (int i = 0; i < 2; ++i)
            creg[i] = cn[((size_t)layer * BATCH + b0 + bq_c * 2 + i) * HH + u_c];
    }
    // gemm mapping: thread (j = tid%200, half = tid/200) computes batches half*8..half*8+7
    const int j_g    = tid % G4;
    const int half_g = (tid < 400) ? (tid / G4) : 0;
    const int bo_g   = half_g * 8;
    __syncthreads();

    int* prog_prev = (layer > 0)      ? &d_prog[s * NL + layer - 1] : 0;
    int* cons_next = (layer < NL - 1) ? &d_cons[s * NL + layer + 1] : 0;
    int* prog_me   = &d_prog[s * NL + layer];
    int* cons_me   = &d_cons[s * NL + layer];

    for (int t = 0; t < TT; ++t) {
        unsigned long long acc2[4];

        // ---- B1: acc = bias + h @ Whh^T (own h, no wait) ----
        if (tid < 400) {
            unsigned long long bj2 = pack2(sm_b[j_g]);
#pragma unroll
            for (int p = 0; p < 4; ++p) acc2[p] = bj2;
#pragma unroll 5
            for (int k = 0; k < HH; ++k) {
                unsigned long long w2 = pack2(sm_whh[k * G4 + j_g]);
                const ulonglong2* hp = (const ulonglong2*)(sm_hs + k * 20 + bo_g);
                ulonglong2 q0 = hp[0], q1 = hp[1];
                fma2(acc2[0], q0.x, w2); fma2(acc2[1], q0.y, w2);
                fma2(acc2[2], q1.x, w2); fma2(acc2[3], q1.y, w2);
            }
        }

        // ---- A: waits (uniform block scope) + stage x ----
        if (layer > 0) {
            if (lane == 0) { while (ld_acquire_gpu(prog_prev) < t + 1) __nanosleep(32); }
            __syncwarp();
        }
        if (layer < NL - 1 && t >= RINGN) {
            if (lane == 0) { while (ld_acquire_gpu(cons_next) < t - RINGN + 1) __nanosleep(32); }
            __syncwarp();
        }
        if (layer == 0) {
            for (int idx = tid; idx < K1 * 4; idx += TPB) {
                int d = idx >> 2, q = idx & 3;
                float4 v = *(const float4*)(d_xT + ((size_t)t * DIN + d) * BATCH + b0 + q * 4);
                *(float4*)(sm_xs + d * 20 + q * 4) = v;
            }
        } else {
            const float* rp = d_ring + (((size_t)(layer - 1) * RINGN + (t & (RINGN - 1))) * HH) * BATCH;
            for (int idx = tid; idx < HH * 4; idx += TPB) {
                int u = idx >> 2, q = idx & 3;
                float4 v = __ldcg((const float4*)(rp + u * BATCH + b0 + q * 4));
                *(float4*)(sm_xs + u * 20 + q * 4) = v;
            }
        }
        __syncthreads();
        if (tid == 0 && layer > 0 && (((t & 3) == 3) || t == TT - 1))
            st_release_gpu(cons_me, t + 1);

        // ---- B2: acc += x @ Wih^T ----
        if (tid < 400) {
#pragma unroll 5
            for (int k = 0; k < K1; ++k) {
                unsigned long long w2 = pack2(sm_wih[k * G4 + j_g]);
                const ulonglong2* xp = (const ulonglong2*)(sm_xs + k * 20 + bo_g);
                ulonglong2 q0 = xp[0], q1 = xp[1];
                fma2(acc2[0], q0.x, w2); fma2(acc2[1], q0.y, w2);
                fma2(acc2[2], q1.x, w2); fma2(acc2[3], q1.y, w2);
            }
#pragma unroll
            for (int p = 0; p < 4; ++p) {
                float lo, hi;
                unpack2(acc2[p], lo, hi);
                sm_gs[(bo_g + 2 * p)     * G4 + j_g] = lo;
                sm_gs[(bo_g + 2 * p + 1) * G4 + j_g] = hi;
            }
        }
        __syncthreads();

        // ---- C: cell update (c in regs), publish h (ring or d_hT) ----
        if (tid < 400) {
            const int u  = u_c;
            const int bq = bq_c;
            float h2[2];
#pragma unroll
            for (int i = 0; i < 2; ++i) {
                int b = bq * 2 + i;
                float gi = sm_gs[b * G4 + u];
                float gf = sm_gs[b * G4 + 50 + u];
                float gg = sm_gs[b * G4 + 100 + u];
                float go = sm_gs[b * G4 + 150 + u];
                float c = sigf(gf) * creg[i] + sigf(gi) * tanhfast(gg);
                float h = sigf(go) * tanhfast(c);
                creg[i] = c;
                h2[i] = h;
            }
            *(float2*)(sm_hs + u * 20 + bq * 2) = make_float2(h2[0], h2[1]);
            float2 hv = make_float2(h2[0], h2[1]);
            float* dst = (layer < NL - 1)
                ? (d_ring + (((size_t)layer * RINGN + (t & (RINGN - 1))) * HH + u) * BATCH + b0 + bq * 2)
                : (d_hT + ((size_t)t * HH + u) * BATCH + b0 + bq * 2);
            __stcg((float2*)dst, hv);
            if (t == TT - 1 && has_state) {
                size_t base = (size_t)BATCH * DOUT * TT;
#pragma unroll
                for (int i = 0; i < 2; ++i) {
                    size_t sidx = ((size_t)layer * BATCH + b0 + bq * 2 + i) * HH + u;
                    out[base + sidx] = h2[i];
                    out[base + (size_t)NL * BATCH * HH + sidx] = creg[i];
                }
            }
        }
        __syncthreads();

        // ---- D: publish progress ----
        if (tid == 0) st_release_gpu(prog_me, t + 1);
    }
}

extern "C" void kernel_launch(void* const* d_in, const int* in_sizes, int n_in,
                              void* d_out, int out_size) {
    const float* x    = (const float*)d_in[0];
    const float* hn   = (const float*)d_in[1];
    const float* cn   = (const float*)d_in[2];
    const float* Wih0 = (const float*)d_in[3];
    const float* Wih  = (const float*)d_in[4];
    const float* Whh  = (const float*)d_in[5];
    const float* bih  = (const float*)d_in[6];
    const float* bhh  = (const float*)d_in[7];
    const float* fcw  = (const float*)d_in[8];
    const float* fcb  = (const float*)d_in[9];
    float* out = (float*)d_out;

    const long long full = (long long)BATCH * DOUT * TT + 2LL * NL * BATCH * HH;
    int has_state = (out_size >= full) ? 1 : 0;

    cudaFuncSetAttribute(lstm_kernel, cudaFuncAttributeMaxDynamicSharedMemorySize,
                         SMEM_FLOATS * sizeof(float));

    xpose_kernel<<<(BATCH * DIN * TT + 255) / 256, 256>>>(x);
    lstm_kernel<<<NL * NSL + NSL, TPB, SMEM_FLOATS * sizeof(float)>>>(
        hn, cn, Wih0, Wih, Whh, bih, bhh, fcw, fcb, out, has_state);
}